// round 3
// baseline (speedup 1.0000x reference)
#include <cuda_runtime.h>
#include <math.h>

// Problem dims
#define B 128
#define D 512
#define S 512
#define F 1024     // 2*D
#define TOPK 10

// scratch (device globals: allocation-free)
__device__ float g_info[B * D];     // mean over s of x[b,d,:]
__device__ float g_gproj[B * D];    // info_g @ W1b
__device__ float g_spe[S * D];      // pe @ W1 + b1
__device__ float g_scores[B * S];

// ---------------------------------------------------------------------------
// Kernel 1: row means of x (rows are contiguous along s)
__global__ void k_mean(const float* __restrict__ x) {
    int row = blockIdx.x * 8 + (threadIdx.x >> 5);   // row = b*D + d
    int lane = threadIdx.x & 31;
    const float4* p = (const float4*)(x + (size_t)row * S);
    float s = 0.f;
    #pragma unroll
    for (int i = lane; i < S / 4; i += 32) {
        float4 v = p[i];
        s += v.x + v.y + v.z + v.w;
    }
    #pragma unroll
    for (int o = 16; o; o >>= 1) s += __shfl_xor_sync(0xffffffffu, s, o);
    if (lane == 0) g_info[row] = s * (1.0f / (float)S);
}

// ---------------------------------------------------------------------------
// Kernel 2: feat[b,s,d] = x[b,d,s]  (32x32 smem tiles)
__global__ void k_transpose(const float* __restrict__ x, float* __restrict__ feat) {
    __shared__ float tile[32][33];
    int b = blockIdx.z;
    int d0 = blockIdx.y * 32, s0 = blockIdx.x * 32;
    const float* xb = x + (size_t)b * D * S;
    float* fb = feat + (size_t)b * S * D;
    #pragma unroll
    for (int i = threadIdx.y; i < 32; i += 8)
        tile[i][threadIdx.x] = xb[(size_t)(d0 + i) * S + s0 + threadIdx.x];
    __syncthreads();
    #pragma unroll
    for (int i = threadIdx.y; i < 32; i += 8)
        fb[(size_t)(s0 + i) * D + d0 + threadIdx.x] = tile[threadIdx.x][i];
}

// ---------------------------------------------------------------------------
// Kernel 3: spe[s,d] = sum_f pe[s,f]*w1[f,d] + b1[d]   (4 s-rows per block)
__global__ void k_spe(const float* __restrict__ w1, const float* __restrict__ b1) {
    __shared__ float pes[4][128];
    int tid = threadIdx.x;
    int s0 = blockIdx.x * 4;
    int d1 = tid, d2 = tid + 256;
    float acc[4][2] = {};
    for (int f0 = 0; f0 < F; f0 += 128) {
        __syncthreads();
        for (int v = tid; v < 4 * 128; v += 256) {
            int r = v >> 7, fc = v & 127, f = f0 + fc;
            int fe = f & ~1;
            float div = expf(-9.210340371976184f * (float)fe / (float)F);
            float ang = (float)(s0 + r) * div;
            pes[r][fc] = (f & 1) ? cosf(ang) : sinf(ang);
        }
        __syncthreads();
        for (int fc = 0; fc < 128; fc++) {
            const float* wr = w1 + (size_t)(f0 + fc) * D;
            float wa = wr[d1], wb = wr[d2];
            #pragma unroll
            for (int r = 0; r < 4; r++) {
                acc[r][0] += pes[r][fc] * wa;
                acc[r][1] += pes[r][fc] * wb;
            }
        }
    }
    #pragma unroll
    for (int r = 0; r < 4; r++) {
        g_spe[(size_t)(s0 + r) * D + d1] = acc[r][0] + b1[d1];
        g_spe[(size_t)(s0 + r) * D + d2] = acc[r][1] + b1[d2];
    }
}

// ---------------------------------------------------------------------------
// Kernel 4: g_proj[b,d] = sum_f info_g[b,f] * w1[D+f, d]
__global__ void k_gproj(const float* __restrict__ w1) {
    __shared__ float ig[D];
    int tid = threadIdx.x, b = blockIdx.x;
    ig[tid] = g_info[b * D + tid];
    ig[tid + 256] = g_info[b * D + tid + 256];
    __syncthreads();
    float a0 = 0.f, a1 = 0.f;
    const float* wb = w1 + (size_t)D * D;   // second half of w1 rows
    for (int f = 0; f < D; f++) {
        float s = ig[f];
        a0 += s * wb[(size_t)f * D + tid];
        a1 += s * wb[(size_t)f * D + tid + 256];
    }
    g_gproj[b * D + tid] = a0;
    g_gproj[b * D + tid + 256] = a1;
}

// ---------------------------------------------------------------------------
// Kernel 5: main fused GEMM -> score
//   hidden[b,s,d] = feat[b,s,:]·w1[:D, d] + spe[s,d] + gproj[b,d]
//   score[b,s]    = sum_d relu(hidden)*w2[d]
// Tiling: block = (b, 64 s-rows); N processed in 2 chunks of 256; BK=16.
// Thread micro-tile: 8 rows x 8 cols, accumulated as packed f32x2 pairs.
#define BM 64
#define BN 256
#define BK 16

__global__ __launch_bounds__(256, 2) void k_gemm(const float* __restrict__ feat,
                                                 const float* __restrict__ w1,
                                                 const float* __restrict__ w2v) {
    __shared__ float As[BM][BK];     // 4 KB
    __shared__ float Bs[BK][BN];     // 16 KB
    __shared__ float w2s[D];         // 2 KB

    int tid = threadIdx.x;
    int b = blockIdx.x >> 3;
    int s0 = (blockIdx.x & 7) * BM;
    const float* A = feat + ((size_t)b * S + s0) * D;

    int lane = tid & 31, wrp = tid >> 5;
    int m0 = wrp * 8;       // 8 rows per thread
    int n0 = lane * 4;      // 4 cols + 4 cols at +128

    w2s[tid] = w2v[tid];
    w2s[tid + 256] = w2v[tid + 256];

    float spart[8] = {0.f, 0.f, 0.f, 0.f, 0.f, 0.f, 0.f, 0.f};

    const int am = tid >> 2;            // A-load row
    const int ak = (tid & 3) * 4;       // A-load k offset
    const int bk = tid >> 4;            // B-load k row
    const int bn = (tid & 15) * 16;     // B-load col offset

    for (int chunk = 0; chunk < 2; chunk++) {
        int nbase = chunk * BN;
        unsigned long long acc[8][4];
        #pragma unroll
        for (int r = 0; r < 8; r++)
            #pragma unroll
            for (int p = 0; p < 4; p++) acc[r][p] = 0ULL;

        for (int f0 = 0; f0 < D; f0 += BK) {
            __syncthreads();
            // A tile: 64x16
            *(float4*)&As[am][ak] = *(const float4*)&A[(size_t)am * D + f0 + ak];
            // B tile: 16x256
            {
                const float* wr = w1 + (size_t)(f0 + bk) * D + nbase + bn;
                *(float4*)&Bs[bk][bn + 0]  = *(const float4*)&wr[0];
                *(float4*)&Bs[bk][bn + 4]  = *(const float4*)&wr[4];
                *(float4*)&Bs[bk][bn + 8]  = *(const float4*)&wr[8];
                *(float4*)&Bs[bk][bn + 12] = *(const float4*)&wr[12];
            }
            __syncthreads();
            #pragma unroll
            for (int k = 0; k < BK; k++) {
                ulonglong2 bp0 = *(const ulonglong2*)&Bs[k][n0];
                ulonglong2 bp1 = *(const ulonglong2*)&Bs[k][128 + n0];
                unsigned long long bb0 = bp0.x, bb1 = bp0.y, bb2 = bp1.x, bb3 = bp1.y;
                #pragma unroll
                for (int r = 0; r < 8; r++) {
                    float a = As[m0 + r][k];
                    unsigned long long a2;
                    asm("mov.b64 %0, {%1, %1};" : "=l"(a2) : "f"(a));
                    asm("fma.rn.f32x2 %0, %1, %2, %0;" : "+l"(acc[r][0]) : "l"(a2), "l"(bb0));
                    asm("fma.rn.f32x2 %0, %1, %2, %0;" : "+l"(acc[r][1]) : "l"(a2), "l"(bb1));
                    asm("fma.rn.f32x2 %0, %1, %2, %0;" : "+l"(acc[r][2]) : "l"(a2), "l"(bb2));
                    asm("fma.rn.f32x2 %0, %1, %2, %0;" : "+l"(acc[r][3]) : "l"(a2), "l"(bb3));
                }
            }
        }

        // epilogue: add spe + gproj, relu, dot w2 into per-row partials
        const float* gp = g_gproj + b * D;
        #pragma unroll
        for (int r = 0; r < 8; r++) {
            int s = s0 + m0 + r;
            const float* sper = g_spe + (size_t)s * D;
            #pragma unroll
            for (int p = 0; p < 4; p++) {
                int nc = (p < 2) ? (n0 + p * 2) : (128 + n0 + (p - 2) * 2);
                int d = nbase + nc;
                float lo, hi;
                asm("mov.b64 {%0, %1}, %2;" : "=f"(lo), "=f"(hi) : "l"(acc[r][p]));
                float v0 = lo + sper[d] + gp[d];
                float v1 = hi + sper[d + 1] + gp[d + 1];
                if (v0 > 0.f) spart[r] += v0 * w2s[d];
                if (v1 > 0.f) spart[r] += v1 * w2s[d + 1];
            }
        }
    }

    // reduce spart across the 32 lanes (all lanes of a warp own the same rows)
    #pragma unroll
    for (int r = 0; r < 8; r++) {
        float v = spart[r];
        #pragma unroll
        for (int o = 16; o; o >>= 1) v += __shfl_xor_sync(0xffffffffu, v, o);
        if (lane == 0) g_scores[b * S + s0 + m0 + r] = v;
    }
}

// ---------------------------------------------------------------------------
// Kernel 6: per-batch top-10 (tie -> lower index, matching lax.top_k),
// sort ascending, emit one-hot indices + gathered features.
__global__ void k_topk(float* __restrict__ out, const float* __restrict__ feat) {
    __shared__ float sv[S];
    __shared__ float rv[S];
    __shared__ int ri[S];
    __shared__ int sel[TOPK];
    int b = blockIdx.x;
    int t = threadIdx.x;   // 512 threads

    sv[t] = g_scores[b * S + t];

    for (int k = 0; k < TOPK; k++) {
        __syncthreads();
        rv[t] = sv[t];
        ri[t] = t;
        __syncthreads();
        for (int str = 256; str > 0; str >>= 1) {
            if (t < str) {
                float v2 = rv[t + str];
                int i2 = ri[t + str];
                if (v2 > rv[t] || (v2 == rv[t] && i2 < ri[t])) { rv[t] = v2; ri[t] = i2; }
            }
            __syncthreads();
        }
        if (t == 0) {
            sel[k] = ri[0];
            sv[ri[0]] = -INFINITY;
        }
    }
    __syncthreads();
    if (t == 0) {
        // insertion sort ascending
        for (int i = 1; i < TOPK; i++) {
            int v = sel[i], j = i - 1;
            while (j >= 0 && sel[j] > v) { sel[j + 1] = sel[j]; j--; }
            sel[j + 1] = v;
        }
    }
    __syncthreads();

    // one-hot indices [B, K, S]
    float* oi = out + (size_t)b * TOPK * S;
    for (int i = t; i < TOPK * S; i += 512) {
        int k = i >> 9, s = i & (S - 1);
        oi[i] = (s == sel[k]) ? 1.0f : 0.0f;
    }
    // selected features [B, K, D]
    float* os = out + (size_t)B * TOPK * S + (size_t)b * TOPK * D;
    const float* fb = feat + (size_t)b * S * D;
    for (int i = t; i < TOPK * D; i += 512) {
        int k = i >> 9, d = i & (D - 1);
        os[i] = fb[(size_t)sel[k] * D + d];
    }
}

// ---------------------------------------------------------------------------
extern "C" void kernel_launch(void* const* d_in, const int* in_sizes, int n_in,
                              void* d_out, int out_size) {
    (void)in_sizes; (void)n_in; (void)out_size;
    const float* x  = (const float*)d_in[0];
    const float* w1 = (const float*)d_in[1];
    const float* b1 = (const float*)d_in[2];
    const float* w2 = (const float*)d_in[3];
    // d_in[4] = b2: constant shift, does not affect top-k ordering -> unused.

    float* out = (float*)d_out;
    // output layout: indices [B,K,S] | selected_feature [B,K,D] | feat [B,S,D]
    float* feat = out + (size_t)B * TOPK * S + (size_t)B * TOPK * D;

    k_mean<<<(B * D) / 8, 256>>>(x);
    k_transpose<<<dim3(S / 32, D / 32, B), dim3(32, 8)>>>(x, feat);
    k_spe<<<S / 4, 256>>>(w1, b1);
    k_gproj<<<B, 256>>>(w1);
    k_gemm<<<B * (S / BM), 256>>>(feat, w1, w2);
    k_topk<<<B, 512>>>(out, feat);
}

// round 6
// speedup vs baseline: 1.3087x; 1.3087x over previous
#include <cuda_runtime.h>
#include <math.h>

// Problem dims
#define B 128
#define D 512
#define S 512
#define F 1024     // 2*D
#define TOPK 10

// scratch (device globals: allocation-free)
__device__ float g_info[B * D];     // mean over s of x[b,d,:]
__device__ float g_gproj[B * D];    // info_g @ W1b
__device__ float g_spe[S * D];      // pe @ W1 + b1
__device__ float g_scores[B * S];

#define FFMA2(acc, a, b) asm("fma.rn.f32x2 %0, %1, %2, %0;" : "+l"(acc) : "l"(a), "l"(b))
#define DUP2(dst, s)     asm("mov.b64 %0, {%1, %1};" : "=l"(dst) : "f"(s))
#define UNPACK2(lo, hi, p) asm("mov.b64 {%0, %1}, %2;" : "=f"(lo), "=f"(hi) : "l"(p))

// ---------------------------------------------------------------------------
// Kernel 1: row means of x (rows are contiguous along s)
__global__ void k_mean(const float* __restrict__ x) {
    int row = blockIdx.x * 8 + (threadIdx.x >> 5);   // row = b*D + d
    int lane = threadIdx.x & 31;
    const float4* p = (const float4*)(x + (size_t)row * S);
    float s = 0.f;
    #pragma unroll
    for (int i = lane; i < S / 4; i += 32) {
        float4 v = p[i];
        s += v.x + v.y + v.z + v.w;
    }
    #pragma unroll
    for (int o = 16; o; o >>= 1) s += __shfl_xor_sync(0xffffffffu, s, o);
    if (lane == 0) g_info[row] = s * (1.0f / (float)S);
}

// ---------------------------------------------------------------------------
// Kernel 2: feat[b,s,d] = x[b,d,s]  (32x32 smem tiles)
__global__ void k_transpose(const float* __restrict__ x, float* __restrict__ feat) {
    __shared__ float tile[32][33];
    int b = blockIdx.z;
    int d0 = blockIdx.y * 32, s0 = blockIdx.x * 32;
    const float* xb = x + (size_t)b * D * S;
    float* fb = feat + (size_t)b * S * D;
    #pragma unroll
    for (int i = threadIdx.y; i < 32; i += 8)
        tile[i][threadIdx.x] = xb[(size_t)(d0 + i) * S + s0 + threadIdx.x];
    __syncthreads();
    #pragma unroll
    for (int i = threadIdx.y; i < 32; i += 8)
        fb[(size_t)(s0 + i) * D + d0 + threadIdx.x] = tile[threadIdx.x][i];
}

// ---------------------------------------------------------------------------
// Kernel 3: spe[s,d] = sum_f pe[s,f]*w1[f,d] + b1[d]
// grid = (S/16) * 4 : 16 s-rows x 128 d-cols per block. FFMA2 over row-pairs.
#define SPE_ROWS 16
__global__ void k_spe(const float* __restrict__ w1, const float* __restrict__ b1) {
    __shared__ float pes[128][SPE_ROWS];   // [fc][row], 8KB
    int tid = threadIdx.x;
    int s0 = (blockIdx.x >> 2) * SPE_ROWS;
    int d0 = (blockIdx.x & 3) * 128;
    int rg = tid >> 7;            // 0/1 -> rows rg*8 .. rg*8+7
    int dc = tid & 127;
    int d = d0 + dc;
    unsigned long long acc2[4] = {0ULL, 0ULL, 0ULL, 0ULL};

    for (int f0 = 0; f0 < F; f0 += 128) {
        __syncthreads();
        for (int v = tid; v < 128 * SPE_ROWS; v += 256) {
            int fc = v >> 4, r = v & 15;
            int f = f0 + fc;
            int fe = f & ~1;
            float div = expf(-9.210340371976184f * (float)fe / (float)F);
            float ang = (float)(s0 + r) * div;
            pes[fc][r] = (f & 1) ? cosf(ang) : sinf(ang);
        }
        __syncthreads();
        #pragma unroll 4
        for (int fc = 0; fc < 128; fc++) {
            float w = w1[(size_t)(f0 + fc) * D + d];
            unsigned long long wd; DUP2(wd, w);
            ulonglong2 p01 = *(const ulonglong2*)&pes[fc][rg * 8];
            ulonglong2 p23 = *(const ulonglong2*)&pes[fc][rg * 8 + 4];
            FFMA2(acc2[0], p01.x, wd);
            FFMA2(acc2[1], p01.y, wd);
            FFMA2(acc2[2], p23.x, wd);
            FFMA2(acc2[3], p23.y, wd);
        }
    }
    float bv = b1[d];
    #pragma unroll
    for (int j = 0; j < 4; j++) {
        float lo, hi;
        UNPACK2(lo, hi, acc2[j]);
        g_spe[(size_t)(s0 + rg * 8 + 2 * j) * D + d]     = lo + bv;
        g_spe[(size_t)(s0 + rg * 8 + 2 * j + 1) * D + d] = hi + bv;
    }
}

// ---------------------------------------------------------------------------
// Kernel 4: g_proj[b,d] = sum_f info_g[b,f] * w1[D+f, d]
// grid = 128 : 16 b-rows x 32 d-cols per block, info tiled in smem.
__global__ void k_gproj(const float* __restrict__ w1) {
    __shared__ float info_s[16][65];
    int tid = threadIdx.x;
    int bt = blockIdx.x >> 4, dt = blockIdx.x & 15;
    int b0 = bt * 16, d0 = dt * 32;
    int dc = tid & 31, bg = tid >> 5;   // bg 0..7 -> 2 b's each
    int d = d0 + dc;
    const float* wb = w1 + (size_t)D * D;
    float acc0 = 0.f, acc1 = 0.f;
    for (int f0 = 0; f0 < D; f0 += 64) {
        __syncthreads();
        for (int v = tid; v < 16 * 64; v += 256) {
            int i = v >> 6, fc = v & 63;
            info_s[i][fc] = g_info[(size_t)(b0 + i) * D + f0 + fc];
        }
        __syncthreads();
        #pragma unroll 4
        for (int fc = 0; fc < 64; fc++) {
            float w = wb[(size_t)(f0 + fc) * D + d];
            acc0 += info_s[bg * 2][fc] * w;
            acc1 += info_s[bg * 2 + 1][fc] * w;
        }
    }
    g_gproj[(size_t)(b0 + bg * 2) * D + d]     = acc0;
    g_gproj[(size_t)(b0 + bg * 2 + 1) * D + d] = acc1;
}

// ---------------------------------------------------------------------------
// Kernel 5: main fused GEMM -> score. A read DIRECTLY from x (k-major tiles),
// cp.async double-buffered smem, 8x8 micro-tile with f32x2 accumulators.
#define BM 64
#define BN 256
#define BK 16
#define NSTEPS (D / BK)   // 32

__global__ __launch_bounds__(256, 2) void k_gemm(const float* __restrict__ x,
                                                 const float* __restrict__ w1,
                                                 const float* __restrict__ w2v) {
    __shared__ float As[2][BK][BM];    // 8 KB
    __shared__ float Bs[2][BK][BN];    // 32 KB
    __shared__ float w2s[D];           // 2 KB

    int tid = threadIdx.x;
    int b = blockIdx.x >> 3;
    int s0 = (blockIdx.x & 7) * BM;
    const float* xb = x + (size_t)b * D * S + s0;   // x[b, f, s0 + ...]

    int lane = tid & 31, wrp = tid >> 5;
    int m0 = wrp * 8;       // 8 rows per thread (whole warp shares rows)
    int n0 = lane * 4;      // 4 cols + 4 cols at +128

    w2s[tid] = w2v[tid];
    w2s[tid + 256] = w2v[tid + 256];

    // tile-load thread mapping
    const int arow = tid >> 4;          // k row (0..15)
    const int acol = (tid & 15) * 4;    // s offset
    const int brow = tid >> 4;          // k row (0..15)
    const int bcol = (tid & 15) * 16;   // n offset

    float spart[8] = {0.f, 0.f, 0.f, 0.f, 0.f, 0.f, 0.f, 0.f};

#define GEMM_PRELOAD(f0, bufi) do {                                            \
    unsigned sa = (unsigned)__cvta_generic_to_shared(&As[bufi][arow][acol]);   \
    asm volatile("cp.async.cg.shared.global [%0], [%1], 16;"                   \
                 :: "r"(sa), "l"(xb + (size_t)((f0) + arow) * S + acol));      \
    const float* wr = w1 + (size_t)((f0) + brow) * D + nbase + bcol;           \
    unsigned sb = (unsigned)__cvta_generic_to_shared(&Bs[bufi][brow][bcol]);   \
    asm volatile("cp.async.cg.shared.global [%0], [%1], 16;" :: "r"(sb), "l"(wr));          \
    asm volatile("cp.async.cg.shared.global [%0], [%1], 16;" :: "r"(sb + 16), "l"(wr + 4)); \
    asm volatile("cp.async.cg.shared.global [%0], [%1], 16;" :: "r"(sb + 32), "l"(wr + 8)); \
    asm volatile("cp.async.cg.shared.global [%0], [%1], 16;" :: "r"(sb + 48), "l"(wr + 12));\
} while (0)

    for (int chunk = 0; chunk < 2; chunk++) {
        int nbase = chunk * BN;
        unsigned long long acc[8][4];
        #pragma unroll
        for (int r = 0; r < 8; r++)
            #pragma unroll
            for (int p = 0; p < 4; p++) acc[r][p] = 0ULL;

        int buf = 0;
        GEMM_PRELOAD(0, 0);
        asm volatile("cp.async.commit_group;");

        for (int step = 0; step < NSTEPS; step++) {
            if (step + 1 < NSTEPS) {
                GEMM_PRELOAD((step + 1) * BK, buf ^ 1);
                asm volatile("cp.async.commit_group;");
                asm volatile("cp.async.wait_group 1;");
            } else {
                asm volatile("cp.async.wait_group 0;");
            }
            __syncthreads();

            #pragma unroll
            for (int k = 0; k < BK; k++) {
                float4 a01 = *(const float4*)&As[buf][k][m0];
                float4 a23 = *(const float4*)&As[buf][k][m0 + 4];
                ulonglong2 bq0 = *(const ulonglong2*)&Bs[buf][k][n0];
                ulonglong2 bq1 = *(const ulonglong2*)&Bs[buf][k][128 + n0];
                float av[8] = {a01.x, a01.y, a01.z, a01.w, a23.x, a23.y, a23.z, a23.w};
                #pragma unroll
                for (int r = 0; r < 8; r++) {
                    unsigned long long a2; DUP2(a2, av[r]);
                    FFMA2(acc[r][0], a2, bq0.x);
                    FFMA2(acc[r][1], a2, bq0.y);
                    FFMA2(acc[r][2], a2, bq1.x);
                    FFMA2(acc[r][3], a2, bq1.y);
                }
            }
            __syncthreads();
            buf ^= 1;
        }

        // epilogue: add spe + gproj, relu, dot w2 into per-row partials
        const float* gp = g_gproj + b * D;
        #pragma unroll
        for (int r = 0; r < 8; r++) {
            int s = s0 + m0 + r;
            const float* sper = g_spe + (size_t)s * D;
            #pragma unroll
            for (int p = 0; p < 4; p++) {
                int nc = (p < 2) ? (n0 + p * 2) : (128 + n0 + (p - 2) * 2);
                int d = nbase + nc;
                float lo, hi;
                UNPACK2(lo, hi, acc[r][p]);
                float v0 = lo + sper[d] + gp[d];
                float v1 = hi + sper[d + 1] + gp[d + 1];
                if (v0 > 0.f) spart[r] += v0 * w2s[d];
                if (v1 > 0.f) spart[r] += v1 * w2s[d + 1];
            }
        }
    }

    // reduce spart across the 32 lanes (all lanes of a warp own the same rows)
    #pragma unroll
    for (int r = 0; r < 8; r++) {
        float v = spart[r];
        #pragma unroll
        for (int o = 16; o; o >>= 1) v += __shfl_xor_sync(0xffffffffu, v, o);
        if (lane == 0) g_scores[b * S + s0 + m0 + r] = v;
    }
}

// ---------------------------------------------------------------------------
// Kernel 6: per-batch top-10 (tie -> lower index, matching lax.top_k),
// sort ascending, emit one-hot indices + gathered features.
__global__ void k_topk(float* __restrict__ out, const float* __restrict__ feat) {
    __shared__ float sv[S];
    __shared__ float rv[S];
    __shared__ int ri[S];
    __shared__ int sel[TOPK];
    int b = blockIdx.x;
    int t = threadIdx.x;   // 512 threads

    sv[t] = g_scores[b * S + t];

    for (int k = 0; k < TOPK; k++) {
        __syncthreads();
        rv[t] = sv[t];
        ri[t] = t;
        __syncthreads();
        for (int str = 256; str > 0; str >>= 1) {
            if (t < str) {
                float v2 = rv[t + str];
                int i2 = ri[t + str];
                if (v2 > rv[t] || (v2 == rv[t] && i2 < ri[t])) { rv[t] = v2; ri[t] = i2; }
            }
            __syncthreads();
        }
        if (t == 0) {
            sel[k] = ri[0];
            sv[ri[0]] = -INFINITY;
        }
    }
    __syncthreads();
    if (t == 0) {
        // insertion sort ascending
        for (int i = 1; i < TOPK; i++) {
            int v = sel[i], j = i - 1;
            while (j >= 0 && sel[j] > v) { sel[j + 1] = sel[j]; j--; }
            sel[j + 1] = v;
        }
    }
    __syncthreads();

    // one-hot indices [B, K, S]
    float* oi = out + (size_t)b * TOPK * S;
    for (int i = t; i < TOPK * S; i += 512) {
        int k = i >> 9, s = i & (S - 1);
        oi[i] = (s == sel[k]) ? 1.0f : 0.0f;
    }
    // selected features [B, K, D]
    float* os = out + (size_t)B * TOPK * S + (size_t)b * TOPK * D;
    const float* fb = feat + (size_t)b * S * D;
    for (int i = t; i < TOPK * D; i += 512) {
        int k = i >> 9, d = i & (D - 1);
        os[i] = fb[(size_t)sel[k] * D + d];
    }
}

// ---------------------------------------------------------------------------
extern "C" void kernel_launch(void* const* d_in, const int* in_sizes, int n_in,
                              void* d_out, int out_size) {
    (void)in_sizes; (void)n_in; (void)out_size;
    const float* x  = (const float*)d_in[0];
    const float* w1 = (const float*)d_in[1];
    const float* b1 = (const float*)d_in[2];
    const float* w2 = (const float*)d_in[3];
    // d_in[4] = b2: constant shift, does not affect top-k ordering -> unused.

    float* out = (float*)d_out;
    // output layout: indices [B,K,S] | selected_feature [B,K,D] | feat [B,S,D]
    float* feat = out + (size_t)B * TOPK * S + (size_t)B * TOPK * D;

    k_mean<<<(B * D) / 8, 256>>>(x);
    k_transpose<<<dim3(S / 32, D / 32, B), dim3(32, 8)>>>(x, feat);
    k_spe<<<(S / SPE_ROWS) * 4, 256>>>(w1, b1);
    k_gproj<<<128, 256>>>(w1);
    k_gemm<<<B * (S / BM), 256>>>(x, w1, w2);
    k_topk<<<B, 512>>>(out, feat);
}